// round 14
// baseline (speedup 1.0000x reference)
#include <cuda_runtime.h>
#include <cuda_bf16.h>

#define DD 64

// ---------------- small statics only (~2.2 MB total; no huge .bss) ----------------
#define NMAX 262144
__device__ int   g_deg[NMAX];
__device__ float g_as[NMAX];
__device__ float g_ad[NMAX];
__device__ float g_emax[NMAX];
__device__ float g_z[NMAX];
__device__ float g_aself[NMAX];
__device__ int   g_e64;

// ---------------- helpers ----------------
__device__ __forceinline__ float leaky02(float x) { return x > 0.f ? x : 0.2f * x; }
__device__ __forceinline__ int clampi(int v, int n) { return v < 0 ? 0 : (v >= n ? n - 1 : v); }

__device__ __forceinline__ int esrc(const int* eidx, int e) {
    return g_e64 ? eidx[2 * e] : eidx[e];
}
__device__ __forceinline__ int edst(const int* eidx, int e, int E) {
    return g_e64 ? eidx[2 * E + 2 * e] : eidx[E + e];
}

__device__ __forceinline__ void atomicMaxFloat(float* addr, float val) {
    if (val >= 0.f) atomicMax((int*)addr, __float_as_int(val));
    else            atomicMin((unsigned int*)addr, __float_as_uint(val));
}

// ---------------- int64-vs-int32 edge detection ----------------
__global__ void k_detect(const int* __restrict__ eidx, int lim) {
    __shared__ int zc, tot;
    if (threadIdx.x == 0) { zc = 0; tot = 0; }
    __syncthreads();
    int lz = 0, lt = 0;
    for (int w = 1 + 2 * (int)threadIdx.x; w < lim; w += 2 * blockDim.x) {
        lt++;
        if (eidx[w] == 0) lz++;
    }
    atomicAdd(&zc, lz); atomicAdd(&tot, lt);
    __syncthreads();
    if (threadIdx.x == 0) g_e64 = (tot > 0 && zc * 10 >= tot * 9) ? 1 : 0;
}

// ---------------- zero agg region + degree ----------------
__global__ void k_zero(float* __restrict__ aggR, int n) {
    int nd = n * DD;
    for (int idx = blockIdx.x * blockDim.x + threadIdx.x; idx < nd;
         idx += gridDim.x * blockDim.x) {
        aggR[idx] = 0.f;
        if (idx < n) g_deg[idx] = 0;
    }
}

// ---------------- fused encoder chain: h = ((relu(ev@W1+b1))@W2+b2)@gcnW ----------
__global__ void k_enc_chain(const float* __restrict__ ev,
                            const float* __restrict__ W1, const float* __restrict__ b1,
                            const float* __restrict__ W2, const float* __restrict__ b2,
                            const float* __restrict__ gcnW,
                            float* __restrict__ hR, int n, int fe) {
    __shared__ float sW1[16 * DD];
    __shared__ float sb1[DD], sb2[DD];
    __shared__ float sW2[DD * DD];
    __shared__ float sWg[DD * DD];
    int cfe = fe > 16 ? 16 : fe;
    for (int t = threadIdx.x; t < cfe * DD; t += blockDim.x) sW1[t] = W1[t];
    for (int t = threadIdx.x; t < DD; t += blockDim.x) { sb1[t] = b1[t]; sb2[t] = b2[t]; }
    for (int t = threadIdx.x; t < DD * DD; t += blockDim.x) { sW2[t] = W2[t]; sWg[t] = gcnW[t]; }
    __syncthreads();
    int i = blockIdx.x * blockDim.x + threadIdx.x;
    if (i >= n) return;
    float A[DD], B[DD];
#pragma unroll
    for (int j = 0; j < DD; j++) A[j] = sb1[j];
    const float* xr = ev + (size_t)i * fe;
    for (int k = 0; k < cfe; k++) {
        float xk = xr[k];
#pragma unroll
        for (int j = 0; j < DD; j++) A[j] += xk * sW1[k * DD + j];
    }
#pragma unroll
    for (int j = 0; j < DD; j++) A[j] = fmaxf(A[j], 0.f);  // hidden
#pragma unroll
    for (int j = 0; j < DD; j++) B[j] = sb2[j];
    for (int k = 0; k < DD; k++) {
        float xk = A[k];
#pragma unroll
        for (int j = 0; j < DD; j++) B[j] += xk * sW2[k * DD + j];
    }                                                       // emb
#pragma unroll
    for (int j = 0; j < DD; j++) A[j] = 0.f;
    for (int k = 0; k < DD; k++) {
        float xk = B[k];
#pragma unroll
        for (int j = 0; j < DD; j++) A[j] += xk * sWg[k * DD + j];
    }                                                       // h_gcn
#pragma unroll
    for (int j = 0; j < DD; j++) hR[(size_t)i * DD + j] = A[j];
}

// ---------------- degree ----------------
__global__ void k_deg(const int* __restrict__ eidx, int n, int E) {
    int e = blockIdx.x * blockDim.x + threadIdx.x;
    if (e < E) atomicAdd(&g_deg[clampi(edst(eidx, e, E), n)], 1);
}

// ---------------- GCN agg: aggR[dst] += hR[src] * rsqrt(ds)*rsqrt(dd) ----------------
__global__ void k_gcn_agg(const int* __restrict__ eidx,
                          const float* __restrict__ hR, float* __restrict__ aggR,
                          int n, int E) {
    int idx = blockIdx.x * blockDim.x + threadIdx.x;
    int e = idx >> 4, c = idx & 15;
    if (e >= E) return;
    int s = clampi(esrc(eidx, e), n), d = clampi(edst(eidx, e, E), n);
    float nm = rsqrtf((float)(g_deg[s] + 1)) * rsqrtf((float)(g_deg[d] + 1));
    float4 v = *((const float4*)hR + (size_t)s * 16 + c);
    float* p = aggR + (size_t)d * DD + c * 4;
    atomicAdd(p + 0, v.x * nm);
    atomicAdd(p + 1, v.y * nm);
    atomicAdd(p + 2, v.z * nm);
    atomicAdd(p + 3, v.w * nm);
}

// ------ x = relu(agg + dinv2*h + gcn_b); h2 = x@gatW (overwrites hR); a_s,a_d,emax ----
__global__ void k_gat_gemm(const float* __restrict__ gatW, const float* __restrict__ gcnb,
                           const float* __restrict__ asrc, const float* __restrict__ adst,
                           float* __restrict__ hR, const float* __restrict__ aggR, int n) {
    __shared__ float sW[DD * DD];
    __shared__ float sgb[DD], ssrc[DD], sdst[DD];
    for (int t = threadIdx.x; t < DD * DD; t += blockDim.x) sW[t] = gatW[t];
    for (int t = threadIdx.x; t < DD; t += blockDim.x) {
        sgb[t] = gcnb[t]; ssrc[t] = asrc[t]; sdst[t] = adst[t];
    }
    __syncthreads();
    int i = blockIdx.x * blockDim.x + threadIdx.x;
    if (i >= n) return;
    float d2 = 1.f / (float)(g_deg[i] + 1);
    float acc[DD];
#pragma unroll
    for (int j = 0; j < DD; j++) acc[j] = 0.f;
    const float* ar = aggR + (size_t)i * DD;
    const float* hr = hR + (size_t)i * DD;
    for (int k = 0; k < DD; k++) {
        float xk = fmaxf(ar[k] + d2 * hr[k] + sgb[k], 0.f);
#pragma unroll
        for (int j = 0; j < DD; j++) acc[j] += xk * sW[k * DD + j];
    }
    float as = 0.f, ad = 0.f;
#pragma unroll
    for (int j = 0; j < DD; j++) {
        hR[(size_t)i * DD + j] = acc[j];   // h2 (row-local overwrite)
        as += acc[j] * ssrc[j];
        ad += acc[j] * sdst[j];
    }
    g_as[i] = as; g_ad[i] = ad;
    g_emax[i] = leaky02(as + ad);          // self-loop seeds max
}

// ---------------- GAT softmax passes (edge logits recomputed, no cache) ----------------
__global__ void k_gat_max(const int* __restrict__ eidx, int n, int E) {
    int e = blockIdx.x * blockDim.x + threadIdx.x;
    if (e >= E) return;
    int s = clampi(esrc(eidx, e), n), d = clampi(edst(eidx, e, E), n);
    atomicMaxFloat(&g_emax[d], leaky02(g_as[s] + g_ad[d]));
}

__global__ void k_zinit(int n) {
    int i = blockIdx.x * blockDim.x + threadIdx.x;
    if (i >= n) return;
    g_z[i] = expf(leaky02(g_as[i] + g_ad[i]) - g_emax[i]);
}

__global__ void k_gat_sum(const int* __restrict__ eidx, int n, int E) {
    int e = blockIdx.x * blockDim.x + threadIdx.x;
    if (e >= E) return;
    int s = clampi(esrc(eidx, e), n), d = clampi(edst(eidx, e, E), n);
    atomicAdd(&g_z[d], expf(leaky02(g_as[s] + g_ad[d]) - g_emax[d]));
}

__global__ void k_alpha_self(int n) {
    int i = blockIdx.x * blockDim.x + threadIdx.x;
    if (i >= n) return;
    g_aself[i] = __fdividef(expf(leaky02(g_as[i] + g_ad[i]) - g_emax[i]), g_z[i]);
}

// aggR = h2 * alpha_self (row-local overwrite of dead GCN agg)
__global__ void k_initagg(const float* __restrict__ hR, float* __restrict__ aggR, int n) {
    int idx = blockIdx.x * blockDim.x + threadIdx.x;
    if (idx >= n * DD) return;
    aggR[idx] = hR[idx] * g_aself[idx >> 6];
}

__global__ void k_gat_agg(const int* __restrict__ eidx,
                          const float* __restrict__ hR, float* __restrict__ aggR,
                          int n, int E) {
    int idx = blockIdx.x * blockDim.x + threadIdx.x;
    int e = idx >> 4, c = idx & 15;
    if (e >= E) return;
    int s = clampi(esrc(eidx, e), n), d = clampi(edst(eidx, e, E), n);
    float alpha = __fdividef(expf(leaky02(g_as[s] + g_ad[d]) - g_emax[d]), g_z[d]);
    float4 v = *((const float4*)hR + (size_t)s * 16 + c);
    float* p = aggR + (size_t)d * DD + c * 4;
    atomicAdd(p + 0, v.x * alpha);
    atomicAdd(p + 1, v.y * alpha);
    atomicAdd(p + 2, v.z * alpha);
    atomicAdd(p + 3, v.w * alpha);
}

// ---------------- fusion GEMMs: fusion = [H, relu(agg + gat_b)] ----------------
// MODE 0: sigmoid -> gate into deltaR (h2 dead). MODE 1: relu -> r1 over aggR (row-local).
template <int MODE>
__global__ void k_fusion(const float* __restrict__ H,
                         const float* __restrict__ W, const float* __restrict__ b,
                         const float* __restrict__ gatb,
                         const float* __restrict__ aggR, float* __restrict__ outR, int n) {
    __shared__ float sW[2 * DD * DD];
    __shared__ float sb[DD], sgb[DD];
    for (int t = threadIdx.x; t < 2 * DD * DD; t += blockDim.x) sW[t] = W[t];
    for (int t = threadIdx.x; t < DD; t += blockDim.x) { sb[t] = b[t]; sgb[t] = gatb[t]; }
    __syncthreads();
    int i = blockIdx.x * blockDim.x + threadIdx.x;
    if (i >= n) return;
    float acc[DD];
#pragma unroll
    for (int j = 0; j < DD; j++) acc[j] = sb[j];
    const float* Hr = H + (size_t)i * DD;
    for (int k = 0; k < DD; k++) {
        float f = Hr[k];
#pragma unroll
        for (int j = 0; j < DD; j++) acc[j] += f * sW[k * DD + j];
    }
    const float* Ar = aggR + (size_t)i * DD;
    for (int k = 0; k < DD; k++) {
        float f = fmaxf(Ar[k] + sgb[k], 0.f);
#pragma unroll
        for (int j = 0; j < DD; j++) acc[j] += f * sW[(DD + k) * DD + j];
    }
#pragma unroll
    for (int j = 0; j < DD; j++) {
        float v = acc[j];
        if (MODE == 0) v = 1.f / (1.f + expf(-v));
        else           v = fmaxf(v, 0.f);
        outR[(size_t)i * DD + j] = v;
    }
}

// ---- final: delta = gate*(r1@resW2+b2); Hfin = H+delta; speed head. Row-local
//      overwrites: gate(deltaR)->delta, r1(hfinR)->Hfin, speed->tail.
__global__ void k_final(const float* __restrict__ H,
                        const float* __restrict__ W2, const float* __restrict__ b2,
                        const float* __restrict__ spW1, const float* __restrict__ spb1,
                        const float* __restrict__ spW2, const float* __restrict__ spb2,
                        float* __restrict__ deltaR, float* __restrict__ hfinR,
                        float* __restrict__ speedR, int n, int wr_sp) {
    __shared__ float sW[DD * DD];
    __shared__ float sb[DD];
    __shared__ float sS1[DD * 32];
    __shared__ float sS1b[32], sS2[32];
    __shared__ float sS2b;
    for (int t = threadIdx.x; t < DD * DD; t += blockDim.x) sW[t] = W2[t];
    for (int t = threadIdx.x; t < DD; t += blockDim.x) sb[t] = b2[t];
    for (int t = threadIdx.x; t < DD * 32; t += blockDim.x) sS1[t] = spW1[t];
    for (int t = threadIdx.x; t < 32; t += blockDim.x) { sS1b[t] = spb1[t]; sS2[t] = spW2[t]; }
    if (threadIdx.x == 0) sS2b = spb2[0];
    __syncthreads();
    int i = blockIdx.x * blockDim.x + threadIdx.x;
    if (i >= n) return;
    float acc[DD];
#pragma unroll
    for (int j = 0; j < DD; j++) acc[j] = sb[j];
    const float* rr = hfinR + (size_t)i * DD;   // r1 currently lives here
    for (int k = 0; k < DD; k++) {
        float f = rr[k];
#pragma unroll
        for (int j = 0; j < DD; j++) acc[j] += f * sW[k * DD + j];
    }
    const float* gr = deltaR + (size_t)i * DD;  // gate currently lives here
    const float* Hr = H + (size_t)i * DD;
    float hf[DD];
#pragma unroll
    for (int j = 0; j < DD; j++) {
        float dl = gr[j] * acc[j];
        hf[j] = Hr[j] + dl;
        acc[j] = dl;                            // keep delta in acc
    }
    // speed head on hf
    float sp[32];
#pragma unroll
    for (int m = 0; m < 32; m++) sp[m] = sS1b[m];
    for (int k = 0; k < DD; k++) {
        float f = hf[k];
#pragma unroll
        for (int m = 0; m < 32; m++) sp[m] += f * sS1[k * 32 + m];
    }
    float p = sS2b;
#pragma unroll
    for (int m = 0; m < 32; m++) p += fmaxf(sp[m], 0.f) * sS2[m];
    // final writes (row-local, after all reads)
#pragma unroll
    for (int j = 0; j < DD; j++) {
        deltaR[(size_t)i * DD + j] = acc[j];
        hfinR[(size_t)i * DD + j] = hf[j];
    }
    if (wr_sp) speedR[i] = p;
}

// ======================= host-side resolution =======================
static const long long LSZ[23] = {6400000, 800000, 3200000, 512, 64, 4096, 64,
                                  4096, 64, 4096, 64, 64, 64, 8192, 64, 8192,
                                  64, 4096, 64, 2048, 32, 32, 1};
static const int PERM_ACS[23] = {0, 2, 3, 5, 4, 6, 1, 9, 11, 10, 12, 13, 14,
                                 7, 8, 15, 17, 16, 18, 19, 21, 20, 22};
static const int PERM_ACI[23] = {2, 4, 6, 3, 5, 1, 11, 10, 12, 9, 14, 13, 8,
                                 7, 0, 16, 18, 15, 17, 20, 22, 19, 21};

static bool match_perm(const int* in_sizes, int n_in, const int* perm, long long mult) {
    if (n_in != 23) return false;
    for (int pos = 0; pos < 23; pos++)
        if ((long long)in_sizes[pos] != LSZ[perm[pos]] * mult) return false;
    return true;
}

extern "C" void kernel_launch(void* const* d_in, const int* in_sizes, int n_in,
                              void* d_out, int out_size) {
    const void* ptr[23] = {0};
    long long N = 100000, E = 1600000;
    int FE = 8;
    bool resolved = false;

    for (int m = 1; m <= 4 && !resolved; m *= 4) {
        if (match_perm(in_sizes, n_in, PERM_ACS, m)) {
            for (int p = 0; p < 23; p++) ptr[PERM_ACS[p]] = d_in[p];
            resolved = true;
        } else if (match_perm(in_sizes, n_in, PERM_ACI, m)) {
            for (int p = 0; p < 23; p++) ptr[PERM_ACI[p]] = d_in[p];
            resolved = true;
        }
    }
    if (!resolved && n_in >= 20) {
        for (int m = 1; m <= 4 && !resolved; m *= 4) {
            long long osz = (long long)out_size;
            if (osz % m) continue;
            osz /= m;
            long long Nc = -1;
            if (osz % 129 == 0) Nc = osz / 129;
            else if (osz % 128 == 0) Nc = osz / 128;
            else if (osz % 64 == 0) Nc = osz / 64;
            if (Nc <= 0) continue;
            int iH = -1, iEv = -1, iEg = -1;
            bool ok = true;
            for (int i = 0; i < n_in; i++) {
                long long sz = (long long)in_sizes[i];
                if (sz % m) { ok = false; break; }
                if (sz / m == 64 * Nc && iH < 0) iH = i;
            }
            if (!ok || iH < 0) continue;
            for (int i = 0; i < n_in; i++) {
                if (i == iH) continue;
                long long sz = (long long)in_sizes[i] / m;
                if (sz >= Nc && sz % Nc == 0 && sz / Nc <= 32 && iEv < 0) iEv = i;
            }
            for (int i = 0; i < n_in; i++) {
                if (i == iH || i == iEv) continue;
                long long sz = (long long)in_sizes[i] / m;
                if (sz > 8192 && sz % 2 == 0 && iEg < 0) iEg = i;
            }
            if (iEv < 0 || iEg < 0) continue;
            N = Nc;
            FE = (int)((long long)in_sizes[iEv] / m / Nc);
            E = (long long)in_sizes[iEg] / m / 2;
            ptr[0] = d_in[iH]; ptr[1] = d_in[iEv]; ptr[2] = d_in[iEg];
            const int cls8192[2] = {13, 15};
            const int cls4096[4] = {5, 7, 9, 17};
            const int cls64[9]   = {4, 6, 8, 10, 11, 12, 14, 16, 18};
            const int cls32[2]   = {20, 21};
            int n8 = 0, n4 = 0, n64c = 0, n32c = 0;
            for (int i = 0; i < n_in; i++) {
                if (i == iH || i == iEv || i == iEg) continue;
                long long sz = (long long)in_sizes[i] / m;
                if (sz == 2 * DD * DD)      { if (n8 < 2) ptr[cls8192[n8++]] = d_in[i]; }
                else if (sz == DD * DD)     { if (n4 < 4) ptr[cls4096[n4++]] = d_in[i]; }
                else if (sz == DD)          { if (n64c < 9) ptr[cls64[n64c++]] = d_in[i]; }
                else if (sz == 32)          { if (n32c < 2) ptr[cls32[n32c++]] = d_in[i]; }
                else if (sz == 1)           ptr[22] = d_in[i];
                else if (sz == DD * 32)     ptr[19] = d_in[i];
                else if (sz == (long long)FE * DD) ptr[3] = d_in[i];
            }
            resolved = true;
        }
    }
    if (!resolved || !ptr[0] || !ptr[1] || !ptr[2]) {
        for (int id = 0; id < 23 && id < n_in; id++) ptr[id] = d_in[id];
        N = 100000; E = 1600000; FE = 8;
    }
    for (int id = 0; id < 23; id++) if (!ptr[id] && id < n_in) ptr[id] = d_in[id];
    if (N > NMAX) N = NMAX;
    if (FE < 1 || FE > 16) FE = 8;

    const float* H      = (const float*)ptr[0];
    const float* ev     = (const float*)ptr[1];
    const int*   eidx   = (const int*)ptr[2];
    const float* encW1  = (const float*)ptr[3];
    const float* encb1  = (const float*)ptr[4];
    const float* encW2  = (const float*)ptr[5];
    const float* encb2  = (const float*)ptr[6];
    const float* gcnW   = (const float*)ptr[7];
    const float* gcnb   = (const float*)ptr[8];
    const float* gatW   = (const float*)ptr[9];
    const float* gatAs  = (const float*)ptr[10];
    const float* gatAd  = (const float*)ptr[11];
    const float* gatb   = (const float*)ptr[12];
    const float* gateW  = (const float*)ptr[13];
    const float* gateb  = (const float*)ptr[14];
    const float* resW1  = (const float*)ptr[15];
    const float* resb1  = (const float*)ptr[16];
    const float* resW2  = (const float*)ptr[17];
    const float* resb2  = (const float*)ptr[18];
    const float* spW1   = (const float*)ptr[19];
    const float* spb1   = (const float*)ptr[20];
    const float* spW2   = (const float*)ptr[21];
    const float* spb2   = (const float*)ptr[22];

    // d_out capacity and region pointers (delta | H_final | speed)
    const long long DLT  = (long long)N * DD;
    const long long FULL = 2 * DLT + N;
    long long osz = (long long)out_size;
    long long cap;
    if (osz == FULL || osz == DLT || osz == 2 * DLT) cap = osz;
    else if (osz == 4 * FULL)                        cap = FULL;
    else if (osz == 4 * DLT)                         cap = DLT;
    else if (osz == 8 * DLT)                         cap = 2 * DLT;
    else                                             cap = osz;

    float* out = (float*)d_out;
    float* deltaR = out;                                        // also h/h2/gate scratch
    float* hfinR  = (cap >= 2 * DLT) ? out + DLT : out;         // also agg/r1 scratch
    float* speedR = (cap >= FULL) ? out + 2 * DLT : out;
    int wr_sp = cap >= FULL ? 1 : 0;

    int n = (int)N, e = (int)E;
    const int TB = 256;
    const int NODE_B = 128;
    int gridN   = (n + NODE_B - 1) / NODE_B;
    int gridE   = (e + TB - 1) / TB;
    long long e16 = 16LL * e;
    int gridE16 = (int)((e16 + TB - 1) / TB);
    int gridND  = (n * DD + TB - 1) / TB;
    int gridNs  = (n + TB - 1) / TB;
    long long dl = 2LL * e;
    int detlim  = (int)(dl < 4096 ? dl : 4096);
    if (detlim < 2) detlim = 2;

    k_detect<<<1, 256>>>(eidx, detlim);
    k_zero<<<gridND, TB>>>(hfinR, n);
    k_enc_chain<<<gridN, NODE_B>>>(ev, encW1, encb1, encW2, encb2, gcnW, deltaR, n, FE);
    k_deg<<<gridE, TB>>>(eidx, n, e);
    k_gcn_agg<<<gridE16, TB>>>(eidx, deltaR, hfinR, n, e);
    k_gat_gemm<<<gridN, NODE_B>>>(gatW, gcnb, gatAs, gatAd, deltaR, hfinR, n);
    k_gat_max<<<gridE, TB>>>(eidx, n, e);
    k_zinit<<<gridNs, TB>>>(n);
    k_gat_sum<<<gridE, TB>>>(eidx, n, e);
    k_alpha_self<<<gridNs, TB>>>(n);
    k_initagg<<<gridND, TB>>>(deltaR, hfinR, n);
    k_gat_agg<<<gridE16, TB>>>(eidx, deltaR, hfinR, n, e);
    k_fusion<0><<<gridN, NODE_B>>>(H, gateW, gateb, gatb, hfinR, deltaR, n);  // gate
    k_fusion<1><<<gridN, NODE_B>>>(H, resW1, resb1, gatb, hfinR, hfinR, n);   // r1
    k_final<<<gridN, NODE_B>>>(H, resW2, resb2, spW1, spb1, spW2, spb2,
                               deltaR, hfinR, speedR, n, wr_sp);
}

// round 16
// speedup vs baseline: 1.2155x; 1.2155x over previous
#include <cuda_runtime.h>
#include <cuda_bf16.h>

#define DD 64

// ---------------- small statics only (~7 MB total; no huge .bss) ----------------
#define NMAX 262144
__device__ int   g_deg[NMAX];
__device__ float g_as[NMAX];
__device__ float g_ad[NMAX];
__device__ float g_emax[NMAX];
__device__ float g_z[NMAX];
__device__ float g_aself[NMAX];   // dinv (pre-GAT) -> alpha_self (post-softmax)
__device__ int   g_e64;

// ---------------- helpers ----------------
__device__ __forceinline__ float leaky02(float x) { return x > 0.f ? x : 0.2f * x; }
__device__ __forceinline__ int clampi(int v, int n) { return v < 0 ? 0 : (v >= n ? n - 1 : v); }

__device__ __forceinline__ int esrc(const int* eidx, int e) {
    return g_e64 ? eidx[2 * e] : eidx[e];
}
__device__ __forceinline__ int edst(const int* eidx, int e, int E) {
    return g_e64 ? eidx[2 * E + 2 * e] : eidx[E + e];
}

__device__ __forceinline__ void atomicMaxFloat(float* addr, float val) {
    if (val >= 0.f) atomicMax((int*)addr, __float_as_int(val));
    else            atomicMin((unsigned int*)addr, __float_as_uint(val));
}

// 16B vector reduction (sm_90+): one L2 atomic op instead of four.
__device__ __forceinline__ void red_add_v4(float* p, float a, float b, float c, float d) {
    asm volatile("red.global.add.v4.f32 [%0], {%1, %2, %3, %4};"
                 :: "l"(p), "f"(a), "f"(b), "f"(c), "f"(d) : "memory");
}

// ---------------- int64-vs-int32 edge detection ----------------
__global__ void k_detect(const int* __restrict__ eidx, int lim) {
    __shared__ int zc, tot;
    if (threadIdx.x == 0) { zc = 0; tot = 0; }
    __syncthreads();
    int lz = 0, lt = 0;
    for (int w = 1 + 2 * (int)threadIdx.x; w < lim; w += 2 * blockDim.x) {
        lt++;
        if (eidx[w] == 0) lz++;
    }
    atomicAdd(&zc, lz); atomicAdd(&tot, lt);
    __syncthreads();
    if (threadIdx.x == 0) g_e64 = (tot > 0 && zc * 10 >= tot * 9) ? 1 : 0;
}

// ---------------- zero agg region + degree ----------------
__global__ void k_zero(float* __restrict__ aggR, int n) {
    int nd = n * DD;
    for (int idx = blockIdx.x * blockDim.x + threadIdx.x; idx < nd;
         idx += gridDim.x * blockDim.x) {
        aggR[idx] = 0.f;
        if (idx < n) g_deg[idx] = 0;
    }
}

// ---------------- fused encoder chain: h = ((relu(ev@W1+b1))@W2+b2)@gcnW ----------
__global__ void k_enc_chain(const float* __restrict__ ev,
                            const float* __restrict__ W1, const float* __restrict__ b1,
                            const float* __restrict__ W2, const float* __restrict__ b2,
                            const float* __restrict__ gcnW,
                            float* __restrict__ hR, int n, int fe) {
    __shared__ float sW1[16 * DD];
    __shared__ float sb1[DD], sb2[DD];
    __shared__ float sW2[DD * DD];
    __shared__ float sWg[DD * DD];
    int cfe = fe > 16 ? 16 : fe;
    for (int t = threadIdx.x; t < cfe * DD; t += blockDim.x) sW1[t] = W1[t];
    for (int t = threadIdx.x; t < DD; t += blockDim.x) { sb1[t] = b1[t]; sb2[t] = b2[t]; }
    for (int t = threadIdx.x; t < DD * DD; t += blockDim.x) { sW2[t] = W2[t]; sWg[t] = gcnW[t]; }
    __syncthreads();
    int i = blockIdx.x * blockDim.x + threadIdx.x;
    if (i >= n) return;
    float A[DD], B[DD];
#pragma unroll
    for (int j = 0; j < DD; j++) A[j] = sb1[j];
    const float* xr = ev + (size_t)i * fe;
    for (int k = 0; k < cfe; k++) {
        float xk = xr[k];
#pragma unroll
        for (int j = 0; j < DD; j++) A[j] += xk * sW1[k * DD + j];
    }
#pragma unroll
    for (int j = 0; j < DD; j++) A[j] = fmaxf(A[j], 0.f);  // hidden
#pragma unroll
    for (int j = 0; j < DD; j++) B[j] = sb2[j];
    for (int k = 0; k < DD; k++) {
        float xk = A[k];
#pragma unroll
        for (int j = 0; j < DD; j++) B[j] += xk * sW2[k * DD + j];
    }                                                       // emb
#pragma unroll
    for (int j = 0; j < DD; j++) A[j] = 0.f;
    for (int k = 0; k < DD; k++) {
        float xk = B[k];
#pragma unroll
        for (int j = 0; j < DD; j++) A[j] += xk * sWg[k * DD + j];
    }                                                       // h_gcn
#pragma unroll
    for (int j = 0; j < DD; j++) hR[(size_t)i * DD + j] = A[j];
}

// ---------------- degree ----------------
__global__ void k_deg(const int* __restrict__ eidx, int n, int E) {
    int e = blockIdx.x * blockDim.x + threadIdx.x;
    if (e < E) atomicAdd(&g_deg[clampi(edst(eidx, e, E), n)], 1);
}

// ---------------- dinv[i] = rsqrt(deg+1): hoists MUFU out of the edge pass --------
__global__ void k_dinv(int n) {
    int i = blockIdx.x * blockDim.x + threadIdx.x;
    if (i < n) g_aself[i] = rsqrtf((float)(g_deg[i] + 1));
}

// ---------------- GCN agg: aggR[dst] += hR[src] * dinv[s]*dinv[d] (v4 red) --------
__global__ void k_gcn_agg(const int* __restrict__ eidx,
                          const float* __restrict__ hR, float* __restrict__ aggR,
                          int n, int E) {
    int idx = blockIdx.x * blockDim.x + threadIdx.x;
    int e = idx >> 4, c = idx & 15;
    if (e >= E) return;
    int s = clampi(esrc(eidx, e), n), d = clampi(edst(eidx, e, E), n);
    float nm = g_aself[s] * g_aself[d];           // FMUL only, no MUFU
    float4 v = *((const float4*)hR + (size_t)s * 16 + c);
    red_add_v4(aggR + (size_t)d * DD + c * 4, v.x * nm, v.y * nm, v.z * nm, v.w * nm);
}

// ------ x = relu(agg + dinv2*h + gcn_b); h2 = x@gatW (overwrites hR); a_s,a_d,emax ----
__global__ void k_gat_gemm(const float* __restrict__ gatW, const float* __restrict__ gcnb,
                           const float* __restrict__ asrc, const float* __restrict__ adst,
                           float* __restrict__ hR, const float* __restrict__ aggR, int n) {
    __shared__ float sW[DD * DD];
    __shared__ float sgb[DD], ssrc[DD], sdst[DD];
    for (int t = threadIdx.x; t < DD * DD; t += blockDim.x) sW[t] = gatW[t];
    for (int t = threadIdx.x; t < DD; t += blockDim.x) {
        sgb[t] = gcnb[t]; ssrc[t] = asrc[t]; sdst[t] = adst[t];
    }
    __syncthreads();
    int i = blockIdx.x * blockDim.x + threadIdx.x;
    if (i >= n) return;
    float d2 = 1.f / (float)(g_deg[i] + 1);
    float acc[DD];
#pragma unroll
    for (int j = 0; j < DD; j++) acc[j] = 0.f;
    const float* ar = aggR + (size_t)i * DD;
    const float* hr = hR + (size_t)i * DD;
    for (int k = 0; k < DD; k++) {
        float xk = fmaxf(ar[k] + d2 * hr[k] + sgb[k], 0.f);
#pragma unroll
        for (int j = 0; j < DD; j++) acc[j] += xk * sW[k * DD + j];
    }
    float as = 0.f, ad = 0.f;
#pragma unroll
    for (int j = 0; j < DD; j++) {
        hR[(size_t)i * DD + j] = acc[j];   // h2 (row-local overwrite)
        as += acc[j] * ssrc[j];
        ad += acc[j] * sdst[j];
    }
    g_as[i] = as; g_ad[i] = ad;
    g_emax[i] = leaky02(as + ad);          // self-loop seeds max
}

// ---------------- GAT softmax passes ----------------
__global__ void k_gat_max(const int* __restrict__ eidx, int n, int E) {
    int e = blockIdx.x * blockDim.x + threadIdx.x;
    if (e >= E) return;
    int s = clampi(esrc(eidx, e), n), d = clampi(edst(eidx, e, E), n);
    atomicMaxFloat(&g_emax[d], leaky02(g_as[s] + g_ad[d]));
}

__global__ void k_zinit(int n) {
    int i = blockIdx.x * blockDim.x + threadIdx.x;
    if (i >= n) return;
    g_z[i] = __expf(leaky02(g_as[i] + g_ad[i]) - g_emax[i]);
}

__global__ void k_gat_sum(const int* __restrict__ eidx, int n, int E) {
    int e = blockIdx.x * blockDim.x + threadIdx.x;
    if (e >= E) return;
    int s = clampi(esrc(eidx, e), n), d = clampi(edst(eidx, e, E), n);
    atomicAdd(&g_z[d], __expf(leaky02(g_as[s] + g_ad[d]) - g_emax[d]));
}

__global__ void k_alpha_self(int n) {
    int i = blockIdx.x * blockDim.x + threadIdx.x;
    if (i >= n) return;
    g_aself[i] = __fdividef(__expf(leaky02(g_as[i] + g_ad[i]) - g_emax[i]), g_z[i]);
}

// aggR = h2 * alpha_self (row-local overwrite of dead GCN agg)
__global__ void k_initagg(const float* __restrict__ hR, float* __restrict__ aggR, int n) {
    int idx = blockIdx.x * blockDim.x + threadIdx.x;
    if (idx >= n * DD) return;
    aggR[idx] = hR[idx] * g_aself[idx >> 6];
}

// GAT agg: leader lane computes alpha (exp+div), shfl-broadcast to the 16-lane group,
// payload moved with one v4 reduction per lane.
__global__ void k_gat_agg(const int* __restrict__ eidx,
                          const float* __restrict__ hR, float* __restrict__ aggR,
                          int n, int E) {
    int idx = blockIdx.x * blockDim.x + threadIdx.x;
    int e = idx >> 4, c = idx & 15;
    bool ok = e < E;
    int s = 0, d = 0;
    if (ok) { s = clampi(esrc(eidx, e), n); d = clampi(edst(eidx, e, E), n); }
    int lane = threadIdx.x & 31;
    float alpha = 0.f;
    if (ok && c == 0)
        alpha = __fdividef(__expf(leaky02(g_as[s] + g_ad[d]) - g_emax[d]), g_z[d]);
    alpha = __shfl_sync(0xffffffffu, alpha, lane & 16, 32);  // group leader broadcast
    if (!ok) return;
    float4 v = *((const float4*)hR + (size_t)s * 16 + c);
    red_add_v4(aggR + (size_t)d * DD + c * 4,
               v.x * alpha, v.y * alpha, v.z * alpha, v.w * alpha);
}

// ---------------- fusion GEMMs: fusion = [H, relu(agg + gat_b)] ----------------
// MODE 0: sigmoid -> gate into deltaR (h2 dead). MODE 1: relu -> r1 over aggR (row-local).
template <int MODE>
__global__ void k_fusion(const float* __restrict__ H,
                         const float* __restrict__ W, const float* __restrict__ b,
                         const float* __restrict__ gatb,
                         const float* __restrict__ aggR, float* __restrict__ outR, int n) {
    __shared__ float sW[2 * DD * DD];
    __shared__ float sb[DD], sgb[DD];
    for (int t = threadIdx.x; t < 2 * DD * DD; t += blockDim.x) sW[t] = W[t];
    for (int t = threadIdx.x; t < DD; t += blockDim.x) { sb[t] = b[t]; sgb[t] = gatb[t]; }
    __syncthreads();
    int i = blockIdx.x * blockDim.x + threadIdx.x;
    if (i >= n) return;
    float acc[DD];
#pragma unroll
    for (int j = 0; j < DD; j++) acc[j] = sb[j];
    const float* Hr = H + (size_t)i * DD;
    for (int k = 0; k < DD; k++) {
        float f = Hr[k];
#pragma unroll
        for (int j = 0; j < DD; j++) acc[j] += f * sW[k * DD + j];
    }
    const float* Ar = aggR + (size_t)i * DD;
    for (int k = 0; k < DD; k++) {
        float f = fmaxf(Ar[k] + sgb[k], 0.f);
#pragma unroll
        for (int j = 0; j < DD; j++) acc[j] += f * sW[(DD + k) * DD + j];
    }
#pragma unroll
    for (int j = 0; j < DD; j++) {
        float v = acc[j];
        if (MODE == 0) v = 1.f / (1.f + __expf(-v));
        else           v = fmaxf(v, 0.f);
        outR[(size_t)i * DD + j] = v;
    }
}

// ---- final: delta = gate*(r1@resW2+b2); Hfin = H+delta; speed head ----
__global__ void k_final(const float* __restrict__ H,
                        const float* __restrict__ W2, const float* __restrict__ b2,
                        const float* __restrict__ spW1, const float* __restrict__ spb1,
                        const float* __restrict__ spW2, const float* __restrict__ spb2,
                        float* __restrict__ deltaR, float* __restrict__ hfinR,
                        float* __restrict__ speedR, int n, int wr_sp) {
    __shared__ float sW[DD * DD];
    __shared__ float sb[DD];
    __shared__ float sS1[DD * 32];
    __shared__ float sS1b[32], sS2[32];
    __shared__ float sS2b;
    for (int t = threadIdx.x; t < DD * DD; t += blockDim.x) sW[t] = W2[t];
    for (int t = threadIdx.x; t < DD; t += blockDim.x) sb[t] = b2[t];
    for (int t = threadIdx.x; t < DD * 32; t += blockDim.x) sS1[t] = spW1[t];
    for (int t = threadIdx.x; t < 32; t += blockDim.x) { sS1b[t] = spb1[t]; sS2[t] = spW2[t]; }
    if (threadIdx.x == 0) sS2b = spb2[0];
    __syncthreads();
    int i = blockIdx.x * blockDim.x + threadIdx.x;
    if (i >= n) return;
    float acc[DD];
#pragma unroll
    for (int j = 0; j < DD; j++) acc[j] = sb[j];
    const float* rr = hfinR + (size_t)i * DD;   // r1 currently lives here
    for (int k = 0; k < DD; k++) {
        float f = rr[k];
#pragma unroll
        for (int j = 0; j < DD; j++) acc[j] += f * sW[k * DD + j];
    }
    const float* gr = deltaR + (size_t)i * DD;  // gate currently lives here
    const float* Hr = H + (size_t)i * DD;
    float hf[DD];
#pragma unroll
    for (int j = 0; j < DD; j++) {
        float dl = gr[j] * acc[j];
        hf[j] = Hr[j] + dl;
        acc[j] = dl;                            // keep delta
    }
    float sp[32];
#pragma unroll
    for (int m = 0; m < 32; m++) sp[m] = sS1b[m];
    for (int k = 0; k < DD; k++) {
        float f = hf[k];
#pragma unroll
        for (int m = 0; m < 32; m++) sp[m] += f * sS1[k * 32 + m];
    }
    float p = sS2b;
#pragma unroll
    for (int m = 0; m < 32; m++) p += fmaxf(sp[m], 0.f) * sS2[m];
#pragma unroll
    for (int j = 0; j < DD; j++) {
        deltaR[(size_t)i * DD + j] = acc[j];
        hfinR[(size_t)i * DD + j] = hf[j];
    }
    if (wr_sp) speedR[i] = p;
}

// ======================= host-side resolution (unchanged, proven) =======================
static const long long LSZ[23] = {6400000, 800000, 3200000, 512, 64, 4096, 64,
                                  4096, 64, 4096, 64, 64, 64, 8192, 64, 8192,
                                  64, 4096, 64, 2048, 32, 32, 1};
static const int PERM_ACS[23] = {0, 2, 3, 5, 4, 6, 1, 9, 11, 10, 12, 13, 14,
                                 7, 8, 15, 17, 16, 18, 19, 21, 20, 22};
static const int PERM_ACI[23] = {2, 4, 6, 3, 5, 1, 11, 10, 12, 9, 14, 13, 8,
                                 7, 0, 16, 18, 15, 17, 20, 22, 19, 21};

static bool match_perm(const int* in_sizes, int n_in, const int* perm, long long mult) {
    if (n_in != 23) return false;
    for (int pos = 0; pos < 23; pos++)
        if ((long long)in_sizes[pos] != LSZ[perm[pos]] * mult) return false;
    return true;
}

extern "C" void kernel_launch(void* const* d_in, const int* in_sizes, int n_in,
                              void* d_out, int out_size) {
    const void* ptr[23] = {0};
    long long N = 100000, E = 1600000;
    int FE = 8;
    bool resolved = false;

    for (int m = 1; m <= 4 && !resolved; m *= 4) {
        if (match_perm(in_sizes, n_in, PERM_ACS, m)) {
            for (int p = 0; p < 23; p++) ptr[PERM_ACS[p]] = d_in[p];
            resolved = true;
        } else if (match_perm(in_sizes, n_in, PERM_ACI, m)) {
            for (int p = 0; p < 23; p++) ptr[PERM_ACI[p]] = d_in[p];
            resolved = true;
        }
    }
    if (!resolved && n_in >= 20) {
        for (int m = 1; m <= 4 && !resolved; m *= 4) {
            long long osz = (long long)out_size;
            if (osz % m) continue;
            osz /= m;
            long long Nc = -1;
            if (osz % 129 == 0) Nc = osz / 129;
            else if (osz % 128 == 0) Nc = osz / 128;
            else if (osz % 64 == 0) Nc = osz / 64;
            if (Nc <= 0) continue;
            int iH = -1, iEv = -1, iEg = -1;
            bool ok = true;
            for (int i = 0; i < n_in; i++) {
                long long sz = (long long)in_sizes[i];
                if (sz % m) { ok = false; break; }
                if (sz / m == 64 * Nc && iH < 0) iH = i;
            }
            if (!ok || iH < 0) continue;
            for (int i = 0; i < n_in; i++) {
                if (i == iH) continue;
                long long sz = (long long)in_sizes[i] / m;
                if (sz >= Nc && sz % Nc == 0 && sz / Nc <= 32 && iEv < 0) iEv = i;
            }
            for (int i = 0; i < n_in; i++) {
                if (i == iH || i == iEv) continue;
                long long sz = (long long)in_sizes[i] / m;
                if (sz > 8192 && sz % 2 == 0 && iEg < 0) iEg = i;
            }
            if (iEv < 0 || iEg < 0) continue;
            N = Nc;
            FE = (int)((long long)in_sizes[iEv] / m / Nc);
            E = (long long)in_sizes[iEg] / m / 2;
            ptr[0] = d_in[iH]; ptr[1] = d_in[iEv]; ptr[2] = d_in[iEg];
            const int cls8192[2] = {13, 15};
            const int cls4096[4] = {5, 7, 9, 17};
            const int cls64[9]   = {4, 6, 8, 10, 11, 12, 14, 16, 18};
            const int cls32[2]   = {20, 21};
            int n8 = 0, n4 = 0, n64c = 0, n32c = 0;
            for (int i = 0; i < n_in; i++) {
                if (i == iH || i == iEv || i == iEg) continue;
                long long sz = (long long)in_sizes[i] / m;
                if (sz == 2 * DD * DD)      { if (n8 < 2) ptr[cls8192[n8++]] = d_in[i]; }
                else if (sz == DD * DD)     { if (n4 < 4) ptr[cls4096[n4++]] = d_in[i]; }
                else if (sz == DD)          { if (n64c < 9) ptr[cls64[n64c++]] = d_in[i]; }
                else if (sz == 32)          { if (n32c < 2) ptr[cls32[n32c++]] = d_in[i]; }
                else if (sz == 1)           ptr[22] = d_in[i];
                else if (sz == DD * 32)     ptr[19] = d_in[i];
                else if (sz == (long long)FE * DD) ptr[3] = d_in[i];
            }
            resolved = true;
        }
    }
    if (!resolved || !ptr[0] || !ptr[1] || !ptr[2]) {
        for (int id = 0; id < 23 && id < n_in; id++) ptr[id] = d_in[id];
        N = 100000; E = 1600000; FE = 8;
    }
    for (int id = 0; id < 23; id++) if (!ptr[id] && id < n_in) ptr[id] = d_in[id];
    if (N > NMAX) N = NMAX;
    if (FE < 1 || FE > 16) FE = 8;

    const float* H      = (const float*)ptr[0];
    const float* ev     = (const float*)ptr[1];
    const int*   eidx   = (const int*)ptr[2];
    const float* encW1  = (const float*)ptr[3];
    const float* encb1  = (const float*)ptr[4];
    const float* encW2  = (const float*)ptr[5];
    const float* encb2  = (const float*)ptr[6];
    const float* gcnW   = (const float*)ptr[7];
    const float* gcnb   = (const float*)ptr[8];
    const float* gatW   = (const float*)ptr[9];
    const float* gatAs  = (const float*)ptr[10];
    const float* gatAd  = (const float*)ptr[11];
    const float* gatb   = (const float*)ptr[12];
    const float* gateW  = (const float*)ptr[13];
    const float* gateb  = (const float*)ptr[14];
    const float* resW1  = (const float*)ptr[15];
    const float* resb1  = (const float*)ptr[16];
    const float* resW2  = (const float*)ptr[17];
    const float* resb2  = (const float*)ptr[18];
    const float* spW1   = (const float*)ptr[19];
    const float* spb1   = (const float*)ptr[20];
    const float* spW2   = (const float*)ptr[21];
    const float* spb2   = (const float*)ptr[22];

    // d_out capacity and region pointers (delta | H_final | speed)
    const long long DLT  = (long long)N * DD;
    const long long FULL = 2 * DLT + N;
    long long osz = (long long)out_size;
    long long cap;
    if (osz == FULL || osz == DLT || osz == 2 * DLT) cap = osz;
    else if (osz == 4 * FULL)                        cap = FULL;
    else if (osz == 4 * DLT)                         cap = DLT;
    else if (osz == 8 * DLT)                         cap = 2 * DLT;
    else                                             cap = osz;

    float* out = (float*)d_out;
    float* deltaR = out;                                        // also h/h2/gate scratch
    float* hfinR  = (cap >= 2 * DLT) ? out + DLT : out;         // also agg/r1 scratch
    float* speedR = (cap >= FULL) ? out + 2 * DLT : out;
    int wr_sp = cap >= FULL ? 1 : 0;

    int n = (int)N, e = (int)E;
    const int TB = 256;
    const int NODE_B = 128;
    int gridN   = (n + NODE_B - 1) / NODE_B;
    int gridE   = (e + TB - 1) / TB;
    long long e16 = 16LL * e;
    int gridE16 = (int)((e16 + TB - 1) / TB);
    int gridND  = (n * DD + TB - 1) / TB;
    int gridNs  = (n + TB - 1) / TB;
    long long dl = 2LL * e;
    int detlim  = (int)(dl < 4096 ? dl : 4096);
    if (detlim < 2) detlim = 2;

    k_detect<<<1, 256>>>(eidx, detlim);
    k_zero<<<gridND, TB>>>(hfinR, n);
    k_enc_chain<<<gridN, NODE_B>>>(ev, encW1, encb1, encW2, encb2, gcnW, deltaR, n, FE);
    k_deg<<<gridE, TB>>>(eidx, n, e);
    k_dinv<<<gridNs, TB>>>(n);
    k_gcn_agg<<<gridE16, TB>>>(eidx, deltaR, hfinR, n, e);
    k_gat_gemm<<<gridN, NODE_B>>>(gatW, gcnb, gatAs, gatAd, deltaR, hfinR, n);
    k_gat_max<<<gridE, TB>>>(eidx, n, e);
    k_zinit<<<gridNs, TB>>>(n);
    k_gat_sum<<<gridE, TB>>>(eidx, n, e);
    k_alpha_self<<<gridNs, TB>>>(n);
    k_initagg<<<gridND, TB>>>(deltaR, hfinR, n);
    k_gat_agg<<<gridE16, TB>>>(eidx, deltaR, hfinR, n, e);
    k_fusion<0><<<gridN, NODE_B>>>(H, gateW, gateb, gatb, hfinR, deltaR, n);  // gate
    k_fusion<1><<<gridN, NODE_B>>>(H, resW1, resb1, gatb, hfinR, hfinR, n);   // r1
    k_final<<<gridN, NODE_B>>>(H, resW2, resb2, spW1, spb1, spW2, spb2,
                               deltaR, hfinR, speedR, n, wr_sp);
}